// round 5
// baseline (speedup 1.0000x reference)
#include <cuda_runtime.h>
#include <cstdint>

#define N_SEQ 512
#define N_RES 384
#define C_M   256
#define C_OUTER 32
#define C_Z   128
#define M_DIM (N_RES * C_OUTER)   // 12288
#define K_DIM N_SEQ               // 512

typedef unsigned long long ull;

// scratch (device globals: allocation-free)
__device__ float g_left[N_SEQ * N_RES * C_OUTER];    // [a][b][c] -> [512][12288]
__device__ float g_right[N_SEQ * N_RES * C_OUTER];   // [a][d][e]
__device__ float g_norm[N_RES * N_RES];              // symmetric mask^T mask

// ---------- packed fp32x2 helpers (full-rate fp32 on sm_103a) ----------
__device__ __forceinline__ ull pack2(float x, float y) {
    ull r; asm("mov.b64 %0, {%1, %2};" : "=l"(r) : "f"(x), "f"(y)); return r;
}
__device__ __forceinline__ void fma2(ull& d, ull a, ull b) {
    asm("fma.rn.f32x2 %0, %1, %2, %3;" : "=l"(d) : "l"(a), "l"(b), "l"(d));
}
__device__ __forceinline__ float lo2(ull v) { return __uint_as_float((unsigned)v); }
__device__ __forceinline__ float hi2(ull v) { return __uint_as_float((unsigned)(v >> 32)); }

// =====================================================================
// Kernel A: LayerNorm + left/right projections + mask, per (a,b) row.
// grid = 512*384 blocks, 256 threads (one thread per channel)
// =====================================================================
__global__ __launch_bounds__(256) void ln_proj_kernel(
    const float* __restrict__ act, const float* __restrict__ mask,
    const float* __restrict__ ln_scale, const float* __restrict__ ln_offset,
    const float* __restrict__ lw, const float* __restrict__ lb,
    const float* __restrict__ rw, const float* __restrict__ rb)
{
    __shared__ float s_xn[C_M];
    __shared__ float s_red[16];
    const int row = blockIdx.x;
    const int tid = threadIdx.x;

    float x = act[row * C_M + tid];
    float s = x, s2 = x * x;
    #pragma unroll
    for (int o = 16; o; o >>= 1) {
        s  += __shfl_xor_sync(~0u, s,  o);
        s2 += __shfl_xor_sync(~0u, s2, o);
    }
    const int w = tid >> 5, l = tid & 31;
    if (l == 0) { s_red[w] = s; s_red[w + 8] = s2; }
    __syncthreads();
    if (tid == 0) {
        float ts = 0.f, ts2 = 0.f;
        #pragma unroll
        for (int i = 0; i < 8; i++) { ts += s_red[i]; ts2 += s_red[i + 8]; }
        float mu  = ts * (1.f / C_M);
        float var = ts2 * (1.f / C_M) - mu * mu;
        s_red[0] = mu;
        s_red[1] = rsqrtf(var + 1e-5f);
    }
    __syncthreads();
    const float mu = s_red[0], rstd = s_red[1];
    s_xn[tid] = (x - mu) * rstd * ln_scale[tid] + ln_offset[tid];
    __syncthreads();

    // 64 outputs (32 left + 32 right), 4 threads per output
    const int j = tid >> 2, q = tid & 3;
    const bool is_left = (j < C_OUTER);
    const float* W = is_left ? lw : rw;
    const int jj = j & (C_OUTER - 1);
    float acc = 0.f;
    const int mbase = q * 64;
    #pragma unroll 8
    for (int i = 0; i < 64; i++)
        acc += s_xn[mbase + i] * W[(mbase + i) * C_OUTER + jj];
    acc += __shfl_xor_sync(~0u, acc, 1);
    acc += __shfl_xor_sync(~0u, acc, 2);
    if (q == 0) {
        float mv = mask[row];
        float v = mv * (acc + (is_left ? lb[jj] : rb[jj]));
        if (is_left) g_left[row * C_OUTER + jj] = v;
        else         g_right[row * C_OUTER + jj] = v;
    }
}

// =====================================================================
// Kernel B: norm[b,d] = sum_a mask[a,b]*mask[a,d]; grid=384, block=384
// =====================================================================
__global__ void norm_kernel(const float* __restrict__ mask)
{
    const int d = blockIdx.x, b = threadIdx.x;
    float acc = 0.f;
    #pragma unroll 4
    for (int a = 0; a < N_SEQ; a++)
        acc += mask[a * N_RES + b] * mask[a * N_RES + d];
    g_norm[d * N_RES + b] = acc;   // symmetric
}

// =====================================================================
// Kernel C: fused GEMM1 (L^T R, 128x128 tile over K=512) + in-tile GEMM2
// (16 pairs x 1024 x 128 with W staged in smem) + bias + norm divide.
// grid = (96,96), 256 threads, 80KB dynamic smem, 2 CTAs/SM.
// =====================================================================
__global__ __launch_bounds__(256, 2) void fused_gemm_kernel(
    const float* __restrict__ ow, const float* __restrict__ ob,
    float* __restrict__ out)
{
    extern __shared__ float sm[];
    // phase1: As = sm[0..4095] (2 bufs x [16][128]); Bs = sm[4096..8191]
    // phase2: Cs = sm[0..16383] ([128][128]); Ws = sm[16384..20479] ([32][128])
    const int tid = threadIdx.x;
    const int m0 = blockIdx.x * 128, n0 = blockIdx.y * 128;
    const int tr = tid >> 4, tc = tid & 15;     // 16x16 thread grid, 8x8 microtile
    const int r0 = tid >> 5;                    // 0..7 (global-load row)
    const int c4 = tid & 31;                    // float4 column

    ull acc[8][4];
    #pragma unroll
    for (int i = 0; i < 8; i++)
        #pragma unroll
        for (int j = 0; j < 4; j++) acc[i][j] = 0ull;

    const float* A = g_left;
    const float* B = g_right;

    // preload chunk 0
    float4 na0 = *(const float4*)&A[(r0    ) * M_DIM + m0 + c4 * 4];
    float4 na1 = *(const float4*)&A[(r0 + 8) * M_DIM + m0 + c4 * 4];
    float4 nb0 = *(const float4*)&B[(r0    ) * M_DIM + n0 + c4 * 4];
    float4 nb1 = *(const float4*)&B[(r0 + 8) * M_DIM + n0 + c4 * 4];
    int buf = 0;
    *(float4*)&sm[buf * 2048 + (r0    ) * 128 + c4 * 4] = na0;
    *(float4*)&sm[buf * 2048 + (r0 + 8) * 128 + c4 * 4] = na1;
    *(float4*)&sm[4096 + buf * 2048 + (r0    ) * 128 + c4 * 4] = nb0;
    *(float4*)&sm[4096 + buf * 2048 + (r0 + 8) * 128 + c4 * 4] = nb1;
    __syncthreads();

    for (int kc = 0; kc < 32; kc++) {
        if (kc < 31) {
            const int k0n = (kc + 1) * 16;
            na0 = *(const float4*)&A[(k0n + r0    ) * M_DIM + m0 + c4 * 4];
            na1 = *(const float4*)&A[(k0n + r0 + 8) * M_DIM + m0 + c4 * 4];
            nb0 = *(const float4*)&B[(k0n + r0    ) * M_DIM + n0 + c4 * 4];
            nb1 = *(const float4*)&B[(k0n + r0 + 8) * M_DIM + n0 + c4 * 4];
        }
        const float* Asb = sm + buf * 2048;
        const float* Bsb = sm + 4096 + buf * 2048;
        #pragma unroll
        for (int k = 0; k < 16; k++) {
            float4 av0 = *(const float4*)&Asb[k * 128 + tr * 8];
            float4 av1 = *(const float4*)&Asb[k * 128 + tr * 8 + 4];
            const ull* bp = (const ull*)&Bsb[k * 128 + tc * 8];
            ull b2_0 = bp[0], b2_1 = bp[1], b2_2 = bp[2], b2_3 = bp[3];
            ull a2[8];
            a2[0] = pack2(av0.x, av0.x); a2[1] = pack2(av0.y, av0.y);
            a2[2] = pack2(av0.z, av0.z); a2[3] = pack2(av0.w, av0.w);
            a2[4] = pack2(av1.x, av1.x); a2[5] = pack2(av1.y, av1.y);
            a2[6] = pack2(av1.z, av1.z); a2[7] = pack2(av1.w, av1.w);
            #pragma unroll
            for (int i = 0; i < 8; i++) {
                fma2(acc[i][0], a2[i], b2_0);
                fma2(acc[i][1], a2[i], b2_1);
                fma2(acc[i][2], a2[i], b2_2);
                fma2(acc[i][3], a2[i], b2_3);
            }
        }
        if (kc < 31) {
            const int nb = buf ^ 1;
            *(float4*)&sm[nb * 2048 + (r0    ) * 128 + c4 * 4] = na0;
            *(float4*)&sm[nb * 2048 + (r0 + 8) * 128 + c4 * 4] = na1;
            *(float4*)&sm[4096 + nb * 2048 + (r0    ) * 128 + c4 * 4] = nb0;
            *(float4*)&sm[4096 + nb * 2048 + (r0 + 8) * 128 + c4 * 4] = nb1;
        }
        __syncthreads();
        buf ^= 1;
    }

    // ---------- phase 2: inter tile -> smem, then x W ----------
    float* Cs = sm;                 // [128][128]
    float* Ws = sm + 16384;         // [32][128]
    #pragma unroll
    for (int i = 0; i < 8; i++) {
        const int rowb = (tr * 8 + i) * 128 + tc * 8;
        #pragma unroll
        for (int j = 0; j < 4; j++) *(ull*)&Cs[rowb + 2 * j] = acc[i][j];
    }

    // 16 (b,d) pairs x 128 f; thread tile = 2 pairs x 4 f
    const int pg = tid >> 5;        // warp id: pairs {2pg, 2pg+1}
    const int fg = tid & 31;        // f = fg*4 .. fg*4+3
    const int p0 = pg * 2;
    const int bi0 = p0 >> 2,        dj0 = p0 & 3;
    const int bi1 = (p0 + 1) >> 2,  dj1 = (p0 + 1) & 3;

    ull o2[2][2] = {{0ull, 0ull}, {0ull, 0ull}};
    for (int ch = 0; ch < 32; ch++) {          // ch == c
        __syncthreads();                       // guards Cs stores (first) / Ws reuse
        #pragma unroll
        for (int q = 0; q < 4; q++) {
            const int i4 = tid + q * 256;
            const int rr = i4 >> 5, cc = i4 & 31;
            *(float4*)&Ws[rr * 128 + cc * 4] =
                *(const float4*)&ow[(ch * 32 + rr) * 128 + cc * 4];
        }
        __syncthreads();
        #pragma unroll
        for (int kk = 0; kk < 32; kk++) {      // kk == e
            const float s0 = Cs[(bi0 * 32 + ch) * 128 + dj0 * 32 + kk];
            const float s1 = Cs[(bi1 * 32 + ch) * 128 + dj1 * 32 + kk];
            const ull* wp = (const ull*)&Ws[kk * 128 + fg * 4];
            const ull w0 = wp[0], w1 = wp[1];
            const ull ps0 = pack2(s0, s0), ps1 = pack2(s1, s1);
            fma2(o2[0][0], ps0, w0); fma2(o2[0][1], ps0, w1);
            fma2(o2[1][0], ps1, w0); fma2(o2[1][1], ps1, w1);
        }
    }

    // epilogue: bias + divide by (eps + norm), fully coalesced float4 stores
    const int b0 = blockIdx.x * 4, d0 = blockIdx.y * 4;
    const float4 bb = *(const float4*)&ob[fg * 4];
    {
        const int b = b0 + bi0, d = d0 + dj0;
        const float inv = 1.f / (1e-3f + g_norm[d * N_RES + b]);
        float4 r;
        r.x = (lo2(o2[0][0]) + bb.x) * inv;
        r.y = (hi2(o2[0][0]) + bb.y) * inv;
        r.z = (lo2(o2[0][1]) + bb.z) * inv;
        r.w = (hi2(o2[0][1]) + bb.w) * inv;
        *(float4*)&out[((size_t)b * N_RES + d) * C_Z + fg * 4] = r;
    }
    {
        const int b = b0 + bi1, d = d0 + dj1;
        const float inv = 1.f / (1e-3f + g_norm[d * N_RES + b]);
        float4 r;
        r.x = (lo2(o2[1][0]) + bb.x) * inv;
        r.y = (hi2(o2[1][0]) + bb.y) * inv;
        r.z = (lo2(o2[1][1]) + bb.z) * inv;
        r.w = (hi2(o2[1][1]) + bb.w) * inv;
        *(float4*)&out[((size_t)b * N_RES + d) * C_Z + fg * 4] = r;
    }
}

// =====================================================================
extern "C" void kernel_launch(void* const* d_in, const int* in_sizes, int n_in,
                              void* d_out, int out_size)
{
    (void)in_sizes; (void)n_in; (void)out_size;
    const float* act       = (const float*)d_in[0];
    const float* mask      = (const float*)d_in[1];
    const float* ln_scale  = (const float*)d_in[2];
    const float* ln_offset = (const float*)d_in[3];
    const float* left_w    = (const float*)d_in[4];
    const float* left_b    = (const float*)d_in[5];
    const float* right_w   = (const float*)d_in[6];
    const float* right_b   = (const float*)d_in[7];
    const float* output_w  = (const float*)d_in[8];
    const float* output_b  = (const float*)d_in[9];
    float* out = (float*)d_out;

    // idempotent, non-stream call; safe under graph capture
    cudaFuncSetAttribute(fused_gemm_kernel,
                         cudaFuncAttributeMaxDynamicSharedMemorySize, 81920);

    ln_proj_kernel<<<N_SEQ * N_RES, 256>>>(act, mask, ln_scale, ln_offset,
                                           left_w, left_b, right_w, right_b);
    norm_kernel<<<N_RES, N_RES>>>(mask);
    dim3 grid(96, 96);
    fused_gemm_kernel<<<grid, 256, 81920>>>(output_w, output_b, out);
}